// round 4
// baseline (speedup 1.0000x reference)
#include <cuda_runtime.h>
#include <cstdint>

// out[src] += edge_attr[e] * x[dst]   (E=1.6M, N=100k, D=32)
// Inputs: edge_index int32 [2,E], edge_attr f32 [E], x f32 [N,32]
// Output: f32 [N,32]

__device__ __forceinline__ void red_add_v4(float* addr, float4 v) {
    asm volatile("red.global.add.v4.f32 [%0], {%1, %2, %3, %4};"
                 :: "l"(addr), "f"(v.x), "f"(v.y), "f"(v.z), "f"(v.w)
                 : "memory");
}

__device__ __forceinline__ float4 ldcg_v4(const float* p) {
    float4 v;
    asm volatile("ld.global.cg.v4.f32 {%0, %1, %2, %3}, [%4];"
                 : "=f"(v.x), "=f"(v.y), "=f"(v.z), "=f"(v.w)
                 : "l"(p));
    return v;
}

// Warp = 4 edge-slots x 8 lanes; each lane covers 4 features (float4).
// 32 edges per warp = 8 groups of 4; software-pipelined in 2 stages of 4.
#define EDGES_PER_WARP 32

__global__ __launch_bounds__(256) void scatter_kernel(
        const int* __restrict__ edge_index,
        const float* __restrict__ edge_attr,
        const float* __restrict__ x,
        float* __restrict__ out,
        int E) {
    int lane = threadIdx.x & 31;
    int slot = lane >> 3;            // 0..3  : which edge in the group of 4
    int fofs = (lane & 7) << 2;      // 0..28 : feature offset (float index)
    int warp = (blockIdx.x * blockDim.x + threadIdx.x) >> 5;
    int base = warp * EDGES_PER_WARP;
    if (base >= E) return;

    if (base + EDGES_PER_WARP <= E) {
        #pragma unroll
        for (int g = 0; g < 2; g++) {
            int e0 = base + g * 16 + slot;

            // ---- stage 1: batch 4 independent gathers (MLP=4+) ----
            int   src[4], dst[4];
            float att[4];
            float4 v[4];
            #pragma unroll
            for (int i = 0; i < 4; i++) {
                int e = e0 + i * 4;
                src[i] = __ldg(&edge_index[e]);
                dst[i] = __ldg(&edge_index[E + e]);
                att[i] = __ldg(&edge_attr[e]);
            }
            #pragma unroll
            for (int i = 0; i < 4; i++)
                v[i] = ldcg_v4(x + (long)dst[i] * 32 + fofs);

            // ---- stage 2: scale + reduce ----
            #pragma unroll
            for (int i = 0; i < 4; i++) {
                float a = att[i];
                v[i].x *= a; v[i].y *= a; v[i].z *= a; v[i].w *= a;
                red_add_v4(out + (long)src[i] * 32 + fofs, v[i]);
            }
        }
    } else {
        for (int i = 0; i < 8; i++) {
            int e = base + i * 4 + slot;
            if (e < E) {
                int src = __ldg(&edge_index[e]);
                int dst = __ldg(&edge_index[E + e]);
                float a = __ldg(&edge_attr[e]);
                float4 v = ldcg_v4(x + (long)dst * 32 + fofs);
                v.x *= a; v.y *= a; v.z *= a; v.w *= a;
                red_add_v4(out + (long)src * 32 + fofs, v);
            }
        }
    }
}

extern "C" void kernel_launch(void* const* d_in, const int* in_sizes, int n_in,
                              void* d_out, int out_size) {
    const int*   edge_index = (const int*)d_in[0];
    const float* edge_attr  = (const float*)d_in[1];
    const float* x          = (const float*)d_in[2];
    float*       out        = (float*)d_out;

    int E = in_sizes[0] / 2;

    // zero the (poisoned) output — memset is graph-capturable and cheap
    cudaMemsetAsync(out, 0, (size_t)out_size * sizeof(float));

    // 32 edges per warp
    int warps   = (E + EDGES_PER_WARP - 1) / EDGES_PER_WARP;
    int threads = 256;                         // 8 warps/block
    int blocks  = (warps * 32 + threads - 1) / threads;
    scatter_kernel<<<blocks, threads>>>(edge_index, edge_attr, x, out, E);
}